// round 1
// baseline (speedup 1.0000x reference)
#include <cuda_runtime.h>

#define BATCH 16
#define C 256
#define D 64
#define NPIX 16384
#define NROWS (BATCH*D)

// Scratch (device globals — no runtime allocation allowed)
__device__ float g_logits[(size_t)BATCH * D * NPIX];   // [b][d][n]  (64 MB)
__device__ float g_W1t[C * D];      // [c][d] : (mk_w @ conv1_w)^T
__device__ float g_b1[D];           // mk_w @ conv1_b
__device__ float g_W2[D * C];       // [d][c] : diag(bn_inv) @ conv2_w @ mv_w, transposed
__device__ float g_bias2[C];        // bn_beta - bn_mean * inv
__device__ float g_rowmax[NROWS];
__device__ float g_rowinv[NROWS];

// ---------------------------------------------------------------------------
// K0: fold the four weight matrices + BN into W1 (64x256) and W2 (256x64)
// ---------------------------------------------------------------------------
__global__ __launch_bounds__(256) void prep_kernel(
    const float* __restrict__ conv1_w, const float* __restrict__ conv1_b,
    const float* __restrict__ mk_w,    const float* __restrict__ mv_w,
    const float* __restrict__ conv2_w, const float* __restrict__ bn_gamma,
    const float* __restrict__ bn_beta, const float* __restrict__ bn_mean,
    const float* __restrict__ bn_var)
{
    int gid = blockIdx.x * blockDim.x + threadIdx.x;
    if (gid < D * C) {
        // W1[d][c] = sum_o mk_w[d][o] * conv1_w[o][c]; stored transposed [c][d]
        int d = gid >> 8;
        int c = gid & 255;
        float s = 0.f;
        for (int o = 0; o < C; o++)
            s = fmaf(mk_w[d * C + o], conv1_w[o * C + c], s);
        g_W1t[c * D + d] = s;
    } else if (gid < 2 * D * C) {
        // W2[o][d] = inv[o] * sum_cp conv2_w[o][cp] * mv_w[cp][d]; stored [d][o]
        int j = gid - D * C;
        int d = j >> 8;
        int o = j & 255;
        float inv = bn_gamma[o] * rsqrtf(bn_var[o] + 1e-5f);
        float s = 0.f;
        for (int cp = 0; cp < C; cp++)
            s = fmaf(conv2_w[o * C + cp], mv_w[cp * D + d], s);
        g_W2[d * C + o] = s * inv;
    } else if (gid < 2 * D * C + D) {
        int d = gid - 2 * D * C;
        float s = 0.f;
        for (int o = 0; o < C; o++)
            s = fmaf(mk_w[d * C + o], conv1_b[o], s);
        g_b1[d] = s;
    } else if (gid < 2 * D * C + D + C) {
        int o = gid - 2 * D * C - D;
        float inv = bn_gamma[o] * rsqrtf(bn_var[o] + 1e-5f);
        g_bias2[o] = bn_beta[o] - bn_mean[o] * inv;
    }
}

// ---------------------------------------------------------------------------
// K1: logits = W1 @ x + b1   -> g_logits [b][d=64][n]
// Block tile: 64 d x 256 pixels, 256 threads, 8x8 register tile per thread.
// ---------------------------------------------------------------------------
__global__ __launch_bounds__(256) void logits_kernel(const float* __restrict__ x)
{
    __shared__ float xs[32][256];   // c-chunk x pixels
    __shared__ float ws[32][64];    // c-chunk x d  (d contiguous)

    int b  = blockIdx.y;
    int n0 = blockIdx.x * 256;
    int tid = threadIdx.x;
    int tp = tid & 31;              // pixel group: pixels tp*4..+3 and 128+tp*4..+3
    int td = tid >> 5;              // d group: d = td*8 .. td*8+7
    const float* xb = x + (size_t)b * C * NPIX;

    float acc[8][8];
#pragma unroll
    for (int i = 0; i < 8; i++)
#pragma unroll
        for (int j = 0; j < 8; j++) acc[i][j] = 0.f;

    for (int c0 = 0; c0 < C; c0 += 32) {
        // stage x tile (32 x 256 floats), coalesced float4
#pragma unroll
        for (int k = 0; k < 8; k++) {
            int idx = tid + k * 256;       // 0..2047 float4 index
            int row = idx >> 6;
            int col = idx & 63;
            ((float4*)xs[row])[col] =
                ((const float4*)(xb + (size_t)(c0 + row) * NPIX + n0))[col];
        }
        // stage W1t slice (fully contiguous)
#pragma unroll
        for (int k = 0; k < 8; k++) {
            int idx = tid + k * 256;
            ((float*)ws)[idx] = g_W1t[c0 * D + idx];
        }
        __syncthreads();

#pragma unroll 8
        for (int c = 0; c < 32; c++) {
            float4 xlo = ((float4*)xs[c])[tp];
            float4 xhi = ((float4*)xs[c])[32 + tp];
            float4 w0  = ((float4*)ws[c])[td * 2];
            float4 w1  = ((float4*)ws[c])[td * 2 + 1];
            float wv[8] = {w0.x, w0.y, w0.z, w0.w, w1.x, w1.y, w1.z, w1.w};
#pragma unroll
            for (int i = 0; i < 8; i++) {
                acc[i][0] = fmaf(wv[i], xlo.x, acc[i][0]);
                acc[i][1] = fmaf(wv[i], xlo.y, acc[i][1]);
                acc[i][2] = fmaf(wv[i], xlo.z, acc[i][2]);
                acc[i][3] = fmaf(wv[i], xlo.w, acc[i][3]);
                acc[i][4] = fmaf(wv[i], xhi.x, acc[i][4]);
                acc[i][5] = fmaf(wv[i], xhi.y, acc[i][5]);
                acc[i][6] = fmaf(wv[i], xhi.z, acc[i][6]);
                acc[i][7] = fmaf(wv[i], xhi.w, acc[i][7]);
            }
        }
        __syncthreads();
    }

#pragma unroll
    for (int i = 0; i < 8; i++) {
        int d = td * 8 + i;
        float bb = g_b1[d];
        float* Lrow = g_logits + ((size_t)(b * D + d)) * NPIX + n0;
        float4 vlo = {acc[i][0] + bb, acc[i][1] + bb, acc[i][2] + bb, acc[i][3] + bb};
        float4 vhi = {acc[i][4] + bb, acc[i][5] + bb, acc[i][6] + bb, acc[i][7] + bb};
        ((float4*)Lrow)[tp]      = vlo;
        ((float4*)Lrow)[32 + tp] = vhi;
    }
}

// ---------------------------------------------------------------------------
// K2: online softmax row reduction over n=16384 per (b,d) row.
// ---------------------------------------------------------------------------
__global__ __launch_bounds__(256) void softmax_reduce_kernel()
{
    __shared__ float sm[256], ss[256];
    int row = blockIdx.x;
    int tid = threadIdx.x;
    const float* L = g_logits + (size_t)row * NPIX;

    float m = -1e30f, s = 0.f;
    for (int i = tid; i < NPIX; i += 256) {
        float v = L[i];
        if (v > m) { s = s * __expf(m - v) + 1.f; m = v; }
        else        s += __expf(v - m);
    }
    sm[tid] = m; ss[tid] = s;
    __syncthreads();
    for (int off = 128; off > 0; off >>= 1) {
        if (tid < off) {
            float m1 = sm[tid], s1 = ss[tid];
            float m2 = sm[tid + off], s2 = ss[tid + off];
            float mn = fmaxf(m1, m2);
            sm[tid] = mn;
            ss[tid] = s1 * __expf(m1 - mn) + s2 * __expf(m2 - mn);
        }
        __syncthreads();
    }
    if (tid == 0) { g_rowmax[row] = sm[0]; g_rowinv[row] = 1.f / ss[0]; }
}

// ---------------------------------------------------------------------------
// K3: p = softmax(logits); colsum over d; out = relu(W2 @ p * scale + bias2 + x)
// Block tile: 128 c x 128 pixels, 256 threads, 8x8 register tile.
// Dynamic smem: ps[64][128] + w2s[64][128] + small arrays.
// ---------------------------------------------------------------------------
__global__ __launch_bounds__(256) void output_kernel(const float* __restrict__ x,
                                                     float* __restrict__ out)
{
    extern __shared__ float sh[];
    float (*ps)[128]  = (float(*)[128])sh;                 // 64*128
    float (*w2s)[128] = (float(*)[128])(sh + 64 * 128);    // 64*128
    float* rm_s    = sh + 2 * 64 * 128;                    // 64
    float* ri_s    = rm_s + 64;                            // 64
    float* cs      = ri_s + 64;                            // 2*128
    float* scale_s = cs + 256;                             // 128
    float* b2_s    = scale_s + 128;                        // 128

    int b  = blockIdx.z;
    int c0 = blockIdx.y * 128;
    int n0 = blockIdx.x * 128;
    int tid = threadIdx.x;

    if (tid < 64) {
        rm_s[tid] = g_rowmax[b * D + tid];
        ri_s[tid] = g_rowinv[b * D + tid];
    }
    if (tid < 128) b2_s[tid] = g_bias2[c0 + tid];
    __syncthreads();

    // logits tile -> probabilities (softmax numerator / row sum)
#pragma unroll
    for (int k = 0; k < 32; k++) {
        int idx = tid + k * 256;
        int d = idx >> 7;
        int p = idx & 127;
        float v = g_logits[((size_t)(b * D + d)) * NPIX + n0 + p];
        ps[d][p] = __expf(v - rm_s[d]) * ri_s[d];
    }
    // W2 tile (coalesced, [d][c])
#pragma unroll
    for (int k = 0; k < 32; k++) {
        int idx = tid + k * 256;
        int d = idx >> 7;
        int c = idx & 127;
        w2s[d][c] = g_W2[d * C + c0 + c];
    }
    __syncthreads();

    // per-pixel column sum over d (double-normalization denominator)
    {
        int pix = tid & 127;
        int grp = tid >> 7;          // 0..1
        float partial = 0.f;
#pragma unroll
        for (int k = 0; k < 32; k++) partial += ps[grp * 32 + k][pix];
        cs[grp * 128 + pix] = partial;
    }
    __syncthreads();
    if (tid < 128) scale_s[tid] = 1.f / (1e-9f + cs[tid] + cs[128 + tid]);
    __syncthreads();

    int tp = tid & 15;     // pixel groups: tp*4..+3 and 64+tp*4..+3
    int tc = tid >> 4;     // c = tc*8 .. tc*8+7
    float acc[8][8];
#pragma unroll
    for (int i = 0; i < 8; i++)
#pragma unroll
        for (int j = 0; j < 8; j++) acc[i][j] = 0.f;

#pragma unroll 8
    for (int k = 0; k < 64; k++) {
        float4 plo = ((float4*)ps[k])[tp];
        float4 phi = ((float4*)ps[k])[16 + tp];
        float4 w0  = ((float4*)w2s[k])[tc * 2];
        float4 w1  = ((float4*)w2s[k])[tc * 2 + 1];
        float wv[8] = {w0.x, w0.y, w0.z, w0.w, w1.x, w1.y, w1.z, w1.w};
#pragma unroll
        for (int i = 0; i < 8; i++) {
            acc[i][0] = fmaf(wv[i], plo.x, acc[i][0]);
            acc[i][1] = fmaf(wv[i], plo.y, acc[i][1]);
            acc[i][2] = fmaf(wv[i], plo.z, acc[i][2]);
            acc[i][3] = fmaf(wv[i], plo.w, acc[i][3]);
            acc[i][4] = fmaf(wv[i], phi.x, acc[i][4]);
            acc[i][5] = fmaf(wv[i], phi.y, acc[i][5]);
            acc[i][6] = fmaf(wv[i], phi.z, acc[i][6]);
            acc[i][7] = fmaf(wv[i], phi.w, acc[i][7]);
        }
    }

    float4 sclo = ((float4*)scale_s)[tp];
    float4 schi = ((float4*)scale_s)[16 + tp];
#pragma unroll
    for (int i = 0; i < 8; i++) {
        int c = tc * 8 + i;
        float bb = b2_s[c];
        const float* xr = x   + ((size_t)(b * C + c0 + c)) * NPIX + n0;
        float*     orow = out + ((size_t)(b * C + c0 + c)) * NPIX + n0;
        float4 xlo = ((const float4*)xr)[tp];
        float4 xhi = ((const float4*)xr)[16 + tp];
        float4 vlo, vhi;
        vlo.x = fmaxf(fmaf(acc[i][0], sclo.x, bb) + xlo.x, 0.f);
        vlo.y = fmaxf(fmaf(acc[i][1], sclo.y, bb) + xlo.y, 0.f);
        vlo.z = fmaxf(fmaf(acc[i][2], sclo.z, bb) + xlo.z, 0.f);
        vlo.w = fmaxf(fmaf(acc[i][3], sclo.w, bb) + xlo.w, 0.f);
        vhi.x = fmaxf(fmaf(acc[i][4], schi.x, bb) + xhi.x, 0.f);
        vhi.y = fmaxf(fmaf(acc[i][5], schi.y, bb) + xhi.y, 0.f);
        vhi.z = fmaxf(fmaf(acc[i][6], schi.z, bb) + xhi.z, 0.f);
        vhi.w = fmaxf(fmaf(acc[i][7], schi.w, bb) + xhi.w, 0.f);
        ((float4*)orow)[tp]      = vlo;
        ((float4*)orow)[16 + tp] = vhi;
    }
}

// ---------------------------------------------------------------------------
extern "C" void kernel_launch(void* const* d_in, const int* in_sizes, int n_in,
                              void* d_out, int out_size)
{
    const float* x       = (const float*)d_in[0];
    const float* conv1_w = (const float*)d_in[1];
    const float* conv1_b = (const float*)d_in[2];
    const float* mk_w    = (const float*)d_in[3];
    const float* mv_w    = (const float*)d_in[4];
    const float* conv2_w = (const float*)d_in[5];
    const float* gamma   = (const float*)d_in[6];
    const float* beta    = (const float*)d_in[7];
    const float* mean    = (const float*)d_in[8];
    const float* var     = (const float*)d_in[9];
    float* out = (float*)d_out;

    const int k3_smem = (2 * 64 * 128 + 64 + 64 + 256 + 128 + 128) * (int)sizeof(float);
    cudaFuncSetAttribute(output_kernel, cudaFuncAttributeMaxDynamicSharedMemorySize, k3_smem);

    prep_kernel<<<130, 256>>>(conv1_w, conv1_b, mk_w, mv_w, conv2_w,
                              gamma, beta, mean, var);

    dim3 g1(NPIX / 256, BATCH);
    logits_kernel<<<g1, 256>>>(x);

    softmax_reduce_kernel<<<NROWS, 256>>>();

    dim3 g3(NPIX / 128, C / 128, BATCH);
    output_kernel<<<g3, 256, k3_smem>>>(x, out);
}

// round 3
// speedup vs baseline: 1.0384x; 1.0384x over previous
#include <cuda_runtime.h>
#include <cuda_bf16.h>
#include <cstdint>

#define BATCH 16
#define C 256
#define D 64
#define NPIX 16384

// ---------------- device scratch (no runtime allocation) -------------------
__device__ float g_exp[(size_t)BATCH * D * NPIX];        // exp(logits) [b][d][n] 64MB
__device__ float g_rowinv[BATCH * D];
__device__ __nv_bfloat16 g_W1p[2 * 64 * 264];            // [plane][d][c] padded rows (264 = 256+8)
__device__ __nv_bfloat16 g_W2p[2 * 256 * 72];            // [plane][c][d] padded rows (72 = 64+8)
__device__ float g_b1[D];
__device__ float g_bias2[C];

// ---------------- helpers ---------------------------------------------------
__device__ __forceinline__ uint32_t smem_u32(const void* p) {
    uint32_t a;
    asm("{ .reg .u64 t; cvta.to.shared.u64 t, %1; cvt.u32.u64 %0, t; }" : "=r"(a) : "l"(p));
    return a;
}
__device__ __forceinline__ void ldm_x4(uint32_t addr, uint32_t* r) {
    asm volatile("ldmatrix.sync.aligned.m8n8.x4.shared.b16 {%0,%1,%2,%3}, [%4];"
        : "=r"(r[0]), "=r"(r[1]), "=r"(r[2]), "=r"(r[3]) : "r"(addr));
}
__device__ __forceinline__ void ldm_x4t(uint32_t addr, uint32_t* r) {
    asm volatile("ldmatrix.sync.aligned.m8n8.x4.trans.shared.b16 {%0,%1,%2,%3}, [%4];"
        : "=r"(r[0]), "=r"(r[1]), "=r"(r[2]), "=r"(r[3]) : "r"(addr));
}
__device__ __forceinline__ void mma_bf16(float* d, const uint32_t* a, uint32_t b0, uint32_t b1) {
    asm volatile(
        "mma.sync.aligned.m16n8k16.row.col.f32.bf16.bf16.f32 "
        "{%0,%1,%2,%3}, {%4,%5,%6,%7}, {%8,%9}, {%0,%1,%2,%3};"
        : "+f"(d[0]), "+f"(d[1]), "+f"(d[2]), "+f"(d[3])
        : "r"(a[0]), "r"(a[1]), "r"(a[2]), "r"(a[3]), "r"(b0), "r"(b1));
}
// exp via FMA-pipe polynomial (no MUFU); rel err ~2e-6
__device__ __forceinline__ float fexp(float v) {
    float t = v * 1.44269504f;
    t = fminf(fmaxf(t, -120.f), 120.f);
    float r = rintf(t);
    float f = t - r;
    float q = 0.0013333558f;
    q = fmaf(q, f, 0.0096181291f);
    q = fmaf(q, f, 0.0555041087f);
    q = fmaf(q, f, 0.2402265069f);
    q = fmaf(q, f, 0.6931471806f);
    q = fmaf(q, f, 1.0f);
    return __int_as_float(((int)r + 127) << 23) * q;
}
__device__ __forceinline__ void split_bf16(float v, __nv_bfloat16& hi, __nv_bfloat16& lo) {
    hi = __float2bfloat16(v);
    lo = __float2bfloat16(v - __bfloat162float(hi));
}

// ---------------------------------------------------------------------------
// K0: fold weights + BN.  W1 = mk_w@conv1_w (64x256) -> padded [d][c] planes;
//     W2 = diag(inv)·conv2_w·mv_w (256x64) -> padded [c][d] planes.
// ---------------------------------------------------------------------------
__global__ __launch_bounds__(256) void prep_kernel(
    const float* __restrict__ conv1_w, const float* __restrict__ conv1_b,
    const float* __restrict__ mk_w,    const float* __restrict__ mv_w,
    const float* __restrict__ conv2_w, const float* __restrict__ bn_gamma,
    const float* __restrict__ bn_beta, const float* __restrict__ bn_mean,
    const float* __restrict__ bn_var)
{
    int gid = blockIdx.x * blockDim.x + threadIdx.x;
    if (gid < D * C) {
        int d = gid >> 8, c = gid & 255;
        float s = 0.f;
        for (int o = 0; o < C; o++)
            s = fmaf(mk_w[d * C + o], conv1_w[o * C + c], s);
        __nv_bfloat16 hi, lo; split_bf16(s, hi, lo);
        g_W1p[d * 264 + c] = hi;
        g_W1p[64 * 264 + d * 264 + c] = lo;
    } else if (gid < 2 * D * C) {
        int j = gid - D * C;
        int c = j >> 6, d = j & 63;
        float inv = bn_gamma[c] * rsqrtf(bn_var[c] + 1e-5f);
        float s = 0.f;
        for (int cp = 0; cp < C; cp++)
            s = fmaf(conv2_w[c * C + cp], mv_w[cp * D + d], s);
        s *= inv;
        __nv_bfloat16 hi, lo; split_bf16(s, hi, lo);
        g_W2p[c * 72 + d] = hi;
        g_W2p[256 * 72 + c * 72 + d] = lo;
    } else if (gid < 2 * D * C + D) {
        int d = gid - 2 * D * C;
        float s = 0.f;
        for (int o = 0; o < C; o++)
            s = fmaf(mk_w[d * C + o], conv1_b[o], s);
        g_b1[d] = s;
    } else if (gid < 2 * D * C + D + C) {
        int c = gid - 2 * D * C - D;
        float inv = bn_gamma[c] * rsqrtf(bn_var[c] + 1e-5f);
        g_bias2[c] = bn_beta[c] - bn_mean[c] * inv;
    }
}

// ---------------------------------------------------------------------------
// K1: e = exp(W1 @ x + b1).  Tile: 128 pix (M) x 64 d (N), K=256.
// A = x^T in K-major smem [c][pix] (stride 272B), ldmatrix.trans.
// B = W1 [d][c] (stride 528B), ldmatrix non-trans.
// ---------------------------------------------------------------------------
#define K1_XH 0
#define K1_XL (K1_XH + 256 * 272)       // 69632
#define K1_W  (K1_XL + 256 * 272)       // 139264 ; 2 planes x 64*528 = 67584
#define K1_B1 (K1_W + 67584)            // 206848
#define K1_SMEM (K1_B1 + 256)

__global__ __launch_bounds__(256) void logits_kernel(const float* __restrict__ x)
{
    extern __shared__ char sh[];
    uint32_t sb = smem_u32(sh);
    float* b1s = (float*)(sh + K1_B1);
    int tid = threadIdx.x, w = tid >> 5, lane = tid & 31;
    int b = blockIdx.y, pix0 = blockIdx.x * 128;

    // stage W1 planes (flat, padded layout is premade)
    {
        const float4* src = (const float4*)g_W1p;
        float4* dst = (float4*)(sh + K1_W);
#pragma unroll
        for (int k = 0; k < 17; k++) {
            int idx = tid + k * 256;
            if (idx < 4224) dst[idx] = src[idx];
        }
    }
    if (tid < 64) b1s[tid] = g_b1[tid];

    // stage x tile -> bf16 hi/lo, K-major [c][pix]
    {
        int p2 = (tid & 63) * 2;
        int cg = tid >> 6;                      // 0..3, 64 c each
        const float* xp = x + ((size_t)b * C + cg * 64) * NPIX + pix0 + p2;
        char* xh = sh + K1_XH + (size_t)cg * 64 * 272 + p2 * 2;
        char* xl = sh + K1_XL + (size_t)cg * 64 * 272 + p2 * 2;
#pragma unroll 4
        for (int j = 0; j < 64; j++) {
            float2 v = *(const float2*)(xp + (size_t)j * NPIX);
            __nv_bfloat16 h0, l0, h1, l1;
            split_bf16(v.x, h0, l0);
            split_bf16(v.y, h1, l1);
            __nv_bfloat162 hp; hp.x = h0; hp.y = h1;
            __nv_bfloat162 lp; lp.x = l0; lp.y = l1;
            *(__nv_bfloat162*)(xh + j * 272) = hp;
            *(__nv_bfloat162*)(xl + j * 272) = lp;
        }
    }
    __syncthreads();

    int wm = w & 3, wn = w >> 2;
    int m0 = wm * 32, n0 = wn * 32;

    // ldmatrix address components
    uint32_t a_k = (lane & 7) + ((lane >> 4) << 3);     // k within 16
    uint32_t a_mo = ((lane >> 3) & 1) * 8;              // m offset 0/8
    uint32_t b_row = lane & 15;
    uint32_t b_co = (lane >> 4) << 4;                   // 0/16 bytes

    float acc[2][4][4];
#pragma unroll
    for (int t = 0; t < 2; t++)
#pragma unroll
        for (int q = 0; q < 4; q++)
#pragma unroll
            for (int i = 0; i < 4; i++) acc[t][q][i] = 0.f;

    for (int kk = 0; kk < 16; kk++) {
        uint32_t ah[2][4], al[2][4];
#pragma unroll
        for (int t = 0; t < 2; t++) {
            uint32_t off = (kk * 16 + a_k) * 272 + (m0 + t * 16 + a_mo) * 2;
            ldm_x4t(sb + K1_XH + off, ah[t]);
            ldm_x4t(sb + K1_XL + off, al[t]);
        }
        uint32_t bh[2][4], bl[2][4];
#pragma unroll
        for (int q = 0; q < 2; q++) {
            uint32_t off = (n0 + q * 16 + b_row) * 528 + kk * 32 + b_co;
            ldm_x4(sb + K1_W + off, bh[q]);
            ldm_x4(sb + K1_W + 33792 + off, bl[q]);
        }
#pragma unroll
        for (int t = 0; t < 2; t++)
#pragma unroll
            for (int q = 0; q < 2; q++) {
                // n-tile 2q   : frags {reg0, reg2}
                mma_bf16(acc[t][q * 2], ah[t], bh[q][0], bh[q][2]);
                mma_bf16(acc[t][q * 2], ah[t], bl[q][0], bl[q][2]);
                mma_bf16(acc[t][q * 2], al[t], bh[q][0], bh[q][2]);
                // n-tile 2q+1 : frags {reg1, reg3}
                mma_bf16(acc[t][q * 2 + 1], ah[t], bh[q][1], bh[q][3]);
                mma_bf16(acc[t][q * 2 + 1], ah[t], bl[q][1], bl[q][3]);
                mma_bf16(acc[t][q * 2 + 1], al[t], bh[q][1], bh[q][3]);
            }
    }

    // epilogue: + b1, exp, store e[d][pix]
    int dbase = n0 + (lane & 3) * 2;
    int prow = pix0 + m0 + (lane >> 2);
#pragma unroll
    for (int t = 0; t < 2; t++) {
        int p0 = prow + t * 16, p1 = p0 + 8;
#pragma unroll
        for (int q = 0; q < 4; q++) {
            int d0 = dbase + q * 8;
            float bb0 = b1s[d0], bb1 = b1s[d0 + 1];
            float* e0 = g_exp + ((size_t)(b * D + d0)) * NPIX;
            float* e1 = e0 + NPIX;
            e0[p0] = fexp(acc[t][q][0] + bb0);
            e1[p0] = fexp(acc[t][q][1] + bb1);
            e0[p1] = fexp(acc[t][q][2] + bb0);
            e1[p1] = fexp(acc[t][q][3] + bb1);
        }
    }
}

// ---------------------------------------------------------------------------
// K2: rowinv = 1 / sum_n e
// ---------------------------------------------------------------------------
__global__ __launch_bounds__(256) void rowsum_kernel()
{
    __shared__ float red[256];
    int row = blockIdx.x;
    const float4* p = (const float4*)(g_exp + (size_t)row * NPIX);
    float s = 0.f;
#pragma unroll
    for (int k = 0; k < 16; k++) {
        float4 v = p[threadIdx.x + k * 256];
        s += (v.x + v.y) + (v.z + v.w);
    }
    red[threadIdx.x] = s;
    __syncthreads();
    for (int o = 128; o > 0; o >>= 1) {
        if (threadIdx.x < o) red[threadIdx.x] += red[threadIdx.x + o];
        __syncthreads();
    }
    if (threadIdx.x == 0) g_rowinv[row] = 1.f / red[0];
}

// ---------------------------------------------------------------------------
// K3: p = e*rowinv; scale = 1/(1e-9+colsum); out = relu(W2@p*scale + bias2 + x)
// Tile: 128 pix (M) x 256 c (N, two phases of 128), K=64.
// ---------------------------------------------------------------------------
#define K3_AH 0
#define K3_AL (64 * 272)                 // 17408
#define K3_W  (2 * 64 * 272)             // 34816 ; 2 planes x 256*144 = 73728
#define K3_RI (K3_W + 73728)             // 108544
#define K3_B2 (K3_RI + 256)
#define K3_CS (K3_B2 + 1024)
#define K3_SC (K3_CS + 2048)
#define K3_SMEM (K3_SC + 512)

__global__ __launch_bounds__(256) void output_kernel(const float* __restrict__ x,
                                                     float* __restrict__ out)
{
    extern __shared__ char sh[];
    uint32_t sb = smem_u32(sh);
    float* ri_s = (float*)(sh + K3_RI);
    float* b2_s = (float*)(sh + K3_B2);
    float* cs   = (float*)(sh + K3_CS);
    float* sc_s = (float*)(sh + K3_SC);
    int tid = threadIdx.x, w = tid >> 5, lane = tid & 31;
    int b = blockIdx.y, pix0 = blockIdx.x * 128;

    if (tid < 64) ri_s[tid] = g_rowinv[b * D + tid];
    b2_s[tid] = g_bias2[tid];
    __syncthreads();

    // stage W2 planes (flat)
    {
        const float4* src = (const float4*)g_W2p;
        float4* dst = (float4*)(sh + K3_W);
#pragma unroll
        for (int k = 0; k < 18; k++) {
            int idx = tid + k * 256;
            if (idx < 4608) dst[idx] = src[idx];
        }
    }
    // stage A: p = e * rowinv -> bf16 hi/lo [d][pix], plus column partial sums
    {
        int p2 = (tid & 63) * 2;
        int dg = tid >> 6;                  // 0..3, 16 d each
        const float* ep = g_exp + ((size_t)(b * D + dg * 16)) * NPIX + pix0 + p2;
        char* ahp = sh + K3_AH + (size_t)dg * 16 * 272 + p2 * 2;
        char* alp = sh + K3_AL + (size_t)dg * 16 * 272 + p2 * 2;
        float s0 = 0.f, s1 = 0.f;
#pragma unroll 4
        for (int j = 0; j < 16; j++) {
            float2 v = *(const float2*)(ep + (size_t)j * NPIX);
            float ri = ri_s[dg * 16 + j];
            v.x *= ri; v.y *= ri;
            s0 += v.x; s1 += v.y;
            __nv_bfloat16 h0, l0, h1, l1;
            split_bf16(v.x, h0, l0);
            split_bf16(v.y, h1, l1);
            __nv_bfloat162 hp; hp.x = h0; hp.y = h1;
            __nv_bfloat162 lp; lp.x = l0; lp.y = l1;
            *(__nv_bfloat162*)(ahp + j * 272) = hp;
            *(__nv_bfloat162*)(alp + j * 272) = lp;
        }
        cs[dg * 128 + p2] = s0;
        cs[dg * 128 + p2 + 1] = s1;
    }
    __syncthreads();
    if (tid < 128)
        sc_s[tid] = 1.f / (1e-9f + cs[tid] + cs[128 + tid] + cs[256 + tid] + cs[384 + tid]);
    __syncthreads();

    int wm = w & 3, wn = w >> 2;
    int m0 = wm * 32;

    uint32_t a_k = (lane & 7) + ((lane >> 4) << 3);
    uint32_t a_mo = ((lane >> 3) & 1) * 8;
    uint32_t b_row = lane & 15;
    uint32_t b_co = (lane >> 4) << 4;

    float scA0 = sc_s[m0 + (lane >> 2)];
    float scB0 = sc_s[m0 + (lane >> 2) + 8];
    float scA1 = sc_s[m0 + 16 + (lane >> 2)];
    float scB1 = sc_s[m0 + 16 + (lane >> 2) + 8];

    for (int ph = 0; ph < 2; ph++) {
        int cb = ph * 128 + wn * 64;
        float acc[2][8][4];
#pragma unroll
        for (int t = 0; t < 2; t++)
#pragma unroll
            for (int q = 0; q < 8; q++)
#pragma unroll
                for (int i = 0; i < 4; i++) acc[t][q][i] = 0.f;

#pragma unroll
        for (int kk = 0; kk < 4; kk++) {
            uint32_t ah[2][4], al[2][4];
#pragma unroll
            for (int t = 0; t < 2; t++) {
                uint32_t off = (kk * 16 + a_k) * 272 + (m0 + t * 16 + a_mo) * 2;
                ldm_x4t(sb + K3_AH + off, ah[t]);
                ldm_x4t(sb + K3_AL + off, al[t]);
            }
#pragma unroll
            for (int q = 0; q < 4; q++) {
                uint32_t off = (cb + q * 16 + b_row) * 144 + kk * 32 + b_co;
                uint32_t bh[4], bl[4];
                ldm_x4(sb + K3_W + off, bh);
                ldm_x4(sb + K3_W + 36864 + off, bl);
#pragma unroll
                for (int t = 0; t < 2; t++) {
                    mma_bf16(acc[t][q * 2], ah[t], bh[0], bh[2]);
                    mma_bf16(acc[t][q * 2], ah[t], bl[0], bl[2]);
                    mma_bf16(acc[t][q * 2], al[t], bh[0], bh[2]);
                    mma_bf16(acc[t][q * 2 + 1], ah[t], bh[1], bh[3]);
                    mma_bf16(acc[t][q * 2 + 1], ah[t], bl[1], bl[3]);
                    mma_bf16(acc[t][q * 2 + 1], al[t], bh[1], bh[3]);
                }
            }
        }

        // epilogue for this c-half
        int prow = pix0 + m0 + (lane >> 2);
#pragma unroll
        for (int t = 0; t < 2; t++) {
            int p0 = prow + t * 16, p1 = p0 + 8;
            float sA = t ? scA1 : scA0;
            float sB = t ? scB1 : scB0;
#pragma unroll
            for (int q = 0; q < 8; q++) {
                int c0 = cb + q * 8 + (lane & 3) * 2;
                float bb0 = b2_s[c0], bb1 = b2_s[c0 + 1];
                const float* x0 = x + ((size_t)(b * C + c0)) * NPIX;
                const float* x1 = x0 + NPIX;
                float* o0 = out + ((size_t)(b * C + c0)) * NPIX;
                float* o1 = o0 + NPIX;
                o0[p0] = fmaxf(fmaf(acc[t][q][0], sA, bb0) + x0[p0], 0.f);
                o1[p0] = fmaxf(fmaf(acc[t][q][1], sA, bb1) + x1[p0], 0.f);
                o0[p1] = fmaxf(fmaf(acc[t][q][2], sB, bb0) + x0[p1], 0.f);
                o1[p1] = fmaxf(fmaf(acc[t][q][3], sB, bb1) + x1[p1], 0.f);
            }
        }
    }
}

// ---------------------------------------------------------------------------
extern "C" void kernel_launch(void* const* d_in, const int* in_sizes, int n_in,
                              void* d_out, int out_size)
{
    const float* x       = (const float*)d_in[0];
    const float* conv1_w = (const float*)d_in[1];
    const float* conv1_b = (const float*)d_in[2];
    const float* mk_w    = (const float*)d_in[3];
    const float* mv_w    = (const float*)d_in[4];
    const float* conv2_w = (const float*)d_in[5];
    const float* gamma   = (const float*)d_in[6];
    const float* beta    = (const float*)d_in[7];
    const float* mean    = (const float*)d_in[8];
    const float* var     = (const float*)d_in[9];
    float* out = (float*)d_out;

    cudaFuncSetAttribute(logits_kernel, cudaFuncAttributeMaxDynamicSharedMemorySize, K1_SMEM);
    cudaFuncSetAttribute(output_kernel, cudaFuncAttributeMaxDynamicSharedMemorySize, K3_SMEM);

    prep_kernel<<<130, 256>>>(conv1_w, conv1_b, mk_w, mv_w, conv2_w,
                              gamma, beta, mean, var);

    dim3 g1(NPIX / 128, BATCH);
    logits_kernel<<<g1, 256, K1_SMEM>>>(x);

    rowsum_kernel<<<BATCH * D, 256>>>();

    dim3 g3(NPIX / 128, BATCH);
    output_kernel<<<g3, 256, K3_SMEM>>>(x, out);
}

// round 4
// speedup vs baseline: 1.5184x; 1.4622x over previous
#include <cuda_runtime.h>
#include <cuda_bf16.h>
#include <cstdint>

#define BATCH 16
#define C 256
#define D 64
#define NPIX 16384

// ---------------- device scratch (no runtime allocation) -------------------
__device__ float g_exp[(size_t)BATCH * D * NPIX];        // exp(logits) [b][d][n] 64MB
__device__ float g_part[BATCH * D * 128];                // per-(row, m-block) partial sums
__device__ float g_rowinv[BATCH * D];
__device__ __nv_bfloat16 g_W1p[2 * 2 * 64 * 136];        // [plane][ck][d][136] padded rows
__device__ __nv_bfloat16 g_W2p[2 * 256 * 72];            // [plane][c][d] padded rows
__device__ float g_b1[D];
__device__ float g_bias2[C];

// ---------------- helpers ---------------------------------------------------
__device__ __forceinline__ uint32_t smem_u32(const void* p) {
    uint32_t a;
    asm("{ .reg .u64 t; cvta.to.shared.u64 t, %1; cvt.u32.u64 %0, t; }" : "=r"(a) : "l"(p));
    return a;
}
__device__ __forceinline__ void ldm_x4(uint32_t addr, uint32_t* r) {
    asm volatile("ldmatrix.sync.aligned.m8n8.x4.shared.b16 {%0,%1,%2,%3}, [%4];"
        : "=r"(r[0]), "=r"(r[1]), "=r"(r[2]), "=r"(r[3]) : "r"(addr));
}
__device__ __forceinline__ void ldm_x4t(uint32_t addr, uint32_t* r) {
    asm volatile("ldmatrix.sync.aligned.m8n8.x4.trans.shared.b16 {%0,%1,%2,%3}, [%4];"
        : "=r"(r[0]), "=r"(r[1]), "=r"(r[2]), "=r"(r[3]) : "r"(addr));
}
__device__ __forceinline__ void mma_bf16(float* d, const uint32_t* a, uint32_t b0, uint32_t b1) {
    asm volatile(
        "mma.sync.aligned.m16n8k16.row.col.f32.bf16.bf16.f32 "
        "{%0,%1,%2,%3}, {%4,%5,%6,%7}, {%8,%9}, {%0,%1,%2,%3};"
        : "+f"(d[0]), "+f"(d[1]), "+f"(d[2]), "+f"(d[3])
        : "r"(a[0]), "r"(a[1]), "r"(a[2]), "r"(a[3]), "r"(b0), "r"(b1));
}
// exp via FMA-pipe polynomial (no MUFU); rel err ~2e-6
__device__ __forceinline__ float fexp(float v) {
    float t = v * 1.44269504f;
    t = fminf(fmaxf(t, -120.f), 120.f);
    float r = rintf(t);
    float f = t - r;
    float q = 0.0013333558f;
    q = fmaf(q, f, 0.0096181291f);
    q = fmaf(q, f, 0.0555041087f);
    q = fmaf(q, f, 0.2402265069f);
    q = fmaf(q, f, 0.6931471806f);
    q = fmaf(q, f, 1.0f);
    return __int_as_float(((int)r + 127) << 23) * q;
}
__device__ __forceinline__ void split_bf16(float v, __nv_bfloat16& hi, __nv_bfloat16& lo) {
    hi = __float2bfloat16(v);
    lo = __float2bfloat16(v - __bfloat162float(hi));
}

// ---------------------------------------------------------------------------
// K0: fold weights + BN into W1 (64x256, chunked padded planes) and W2.
// ---------------------------------------------------------------------------
__global__ __launch_bounds__(256) void prep_kernel(
    const float* __restrict__ conv1_w, const float* __restrict__ conv1_b,
    const float* __restrict__ mk_w,    const float* __restrict__ mv_w,
    const float* __restrict__ conv2_w, const float* __restrict__ bn_gamma,
    const float* __restrict__ bn_beta, const float* __restrict__ bn_mean,
    const float* __restrict__ bn_var)
{
    int gid = blockIdx.x * blockDim.x + threadIdx.x;
    if (gid < D * C) {
        int d = gid >> 8, c = gid & 255;
        float s = 0.f;
        for (int o = 0; o < C; o++)
            s = fmaf(mk_w[d * C + o], conv1_w[o * C + c], s);
        __nv_bfloat16 hi, lo; split_bf16(s, hi, lo);
        int ck = c >> 7, cl = c & 127;
        g_W1p[ck * 8704 + d * 136 + cl] = hi;
        g_W1p[17408 + ck * 8704 + d * 136 + cl] = lo;
    } else if (gid < 2 * D * C) {
        int j = gid - D * C;
        int c = j >> 6, d = j & 63;
        float inv = bn_gamma[c] * rsqrtf(bn_var[c] + 1e-5f);
        float s = 0.f;
        for (int cp = 0; cp < C; cp++)
            s = fmaf(conv2_w[c * C + cp], mv_w[cp * D + d], s);
        s *= inv;
        __nv_bfloat16 hi, lo; split_bf16(s, hi, lo);
        g_W2p[c * 72 + d] = hi;
        g_W2p[256 * 72 + c * 72 + d] = lo;
    } else if (gid < 2 * D * C + D) {
        int d = gid - 2 * D * C;
        float s = 0.f;
        for (int o = 0; o < C; o++)
            s = fmaf(mk_w[d * C + o], conv1_b[o], s);
        g_b1[d] = s;
    } else if (gid < 2 * D * C + D + C) {
        int c = gid - 2 * D * C - D;
        float inv = bn_gamma[c] * rsqrtf(bn_var[c] + 1e-5f);
        g_bias2[c] = bn_beta[c] - bn_mean[c] * inv;
    }
}

// ---------------------------------------------------------------------------
// K1: e = exp(W1 @ x + b1), plus per-block row partial sums.
// Tile 128 pix (M) x 64 d (N), K=256 in two chunks of 128 (single-buffered).
// smem ~103KB -> 2 CTAs/SM.
// ---------------------------------------------------------------------------
#define K1_XH 0
#define K1_XL 34816
#define K1_W  69632           // hi chunk 17408 B, lo at +17408
#define K1_B1 104448
#define K1_SPART 104704       // 64*4 floats
#define K1_SMEM (K1_SPART + 1024)

__global__ __launch_bounds__(256, 2) void logits_kernel(const float* __restrict__ x)
{
    extern __shared__ char sh[];
    uint32_t sb = smem_u32(sh);
    float* b1s   = (float*)(sh + K1_B1);
    float* spart = (float*)(sh + K1_SPART);
    int tid = threadIdx.x, w = tid >> 5, lane = tid & 31;
    int b = blockIdx.y, mblk = blockIdx.x, pix0 = mblk * 128;

    if (tid < 64) b1s[tid] = g_b1[tid];

    int wm = w & 3, wn = w >> 2;
    int m0 = wm * 32, n0 = wn * 32;
    uint32_t a_k = (lane & 7) + ((lane >> 4) << 3);
    uint32_t a_mo = ((lane >> 3) & 1) * 8;
    uint32_t b_row = lane & 15;
    uint32_t b_co = (lane >> 4) << 4;

    float acc[2][4][4];
#pragma unroll
    for (int t = 0; t < 2; t++)
#pragma unroll
        for (int q = 0; q < 4; q++)
#pragma unroll
            for (int i = 0; i < 4; i++) acc[t][q][i] = 0.f;

    for (int ck = 0; ck < 2; ck++) {
        // stage W1 chunk (both planes, flat copy of pre-padded layout)
        {
            const float4* src = (const float4*)g_W1p;
            float4* dh = (float4*)(sh + K1_W);
            float4* dl = (float4*)(sh + K1_W + 17408);
            int b0 = ck * 1088, b1o = 2176 + ck * 1088;
#pragma unroll
            for (int k = 0; k < 5; k++) {
                int idx = tid + k * 256;
                if (idx < 1088) { dh[idx] = src[b0 + idx]; dl[idx] = src[b1o + idx]; }
            }
        }
        // stage x chunk -> bf16 hi/lo K-major [c_local][pix], batched loads
        {
            int p2 = (tid & 63) * 2;
            int cg = tid >> 6;                       // 0..3 : 32 c rows each
            const float* xp = x + ((size_t)b * C + ck * 128 + cg * 32) * NPIX + pix0 + p2;
            char* xh = sh + K1_XH + (size_t)cg * 32 * 272 + p2 * 2;
            char* xl = sh + K1_XL + (size_t)cg * 32 * 272 + p2 * 2;
#pragma unroll
            for (int jb = 0; jb < 4; jb++) {
                float2 v[8];
#pragma unroll
                for (int u = 0; u < 8; u++)
                    v[u] = *(const float2*)(xp + (size_t)(jb * 8 + u) * NPIX);
#pragma unroll
                for (int u = 0; u < 8; u++) {
                    int j = jb * 8 + u;
                    __nv_bfloat16 h0, l0, h1, l1;
                    split_bf16(v[u].x, h0, l0);
                    split_bf16(v[u].y, h1, l1);
                    __nv_bfloat162 hp; hp.x = h0; hp.y = h1;
                    __nv_bfloat162 lp; lp.x = l0; lp.y = l1;
                    *(__nv_bfloat162*)(xh + j * 272) = hp;
                    *(__nv_bfloat162*)(xl + j * 272) = lp;
                }
            }
        }
        __syncthreads();

#pragma unroll 2
        for (int kk = 0; kk < 8; kk++) {
            uint32_t ah[2][4], al[2][4];
#pragma unroll
            for (int t = 0; t < 2; t++) {
                uint32_t off = (kk * 16 + a_k) * 272 + (m0 + t * 16 + a_mo) * 2;
                ldm_x4t(sb + K1_XH + off, ah[t]);
                ldm_x4t(sb + K1_XL + off, al[t]);
            }
            uint32_t bh[2][4], bl[2][4];
#pragma unroll
            for (int q = 0; q < 2; q++) {
                uint32_t off = (n0 + q * 16 + b_row) * 272 + kk * 32 + b_co;
                ldm_x4(sb + K1_W + off, bh[q]);
                ldm_x4(sb + K1_W + 17408 + off, bl[q]);
            }
#pragma unroll
            for (int t = 0; t < 2; t++)
#pragma unroll
                for (int q = 0; q < 2; q++) {
                    mma_bf16(acc[t][q * 2], ah[t], bh[q][0], bh[q][2]);
                    mma_bf16(acc[t][q * 2], ah[t], bl[q][0], bl[q][2]);
                    mma_bf16(acc[t][q * 2], al[t], bh[q][0], bh[q][2]);
                    mma_bf16(acc[t][q * 2 + 1], ah[t], bh[q][1], bh[q][3]);
                    mma_bf16(acc[t][q * 2 + 1], ah[t], bl[q][1], bl[q][3]);
                    mma_bf16(acc[t][q * 2 + 1], al[t], bh[q][1], bh[q][3]);
                }
        }
        __syncthreads();
    }

    // epilogue: +b1, exp, store e; accumulate per-d row partials
    int dbase = n0 + (lane & 3) * 2;
    int prow = pix0 + m0 + (lane >> 2);
#pragma unroll
    for (int q = 0; q < 4; q++) {
        int d0 = dbase + q * 8;
        float bb0 = b1s[d0], bb1 = b1s[d0 + 1];
        float* e0 = g_exp + ((size_t)(b * D + d0)) * NPIX;
        float* e1 = e0 + NPIX;
        float s0 = 0.f, s1 = 0.f;
#pragma unroll
        for (int t = 0; t < 2; t++) {
            int p0 = prow + t * 16, p1 = p0 + 8;
            float v00 = fexp(acc[t][q][0] + bb0); e0[p0] = v00;
            float v01 = fexp(acc[t][q][1] + bb1); e1[p0] = v01;
            float v02 = fexp(acc[t][q][2] + bb0); e0[p1] = v02;
            float v03 = fexp(acc[t][q][3] + bb1); e1[p1] = v03;
            s0 += v00 + v02; s1 += v01 + v03;
        }
        // reduce over the 8 lanes sharing (lane & 3)
        s0 += __shfl_xor_sync(0xFFFFFFFF, s0, 4);
        s0 += __shfl_xor_sync(0xFFFFFFFF, s0, 8);
        s0 += __shfl_xor_sync(0xFFFFFFFF, s0, 16);
        s1 += __shfl_xor_sync(0xFFFFFFFF, s1, 4);
        s1 += __shfl_xor_sync(0xFFFFFFFF, s1, 8);
        s1 += __shfl_xor_sync(0xFFFFFFFF, s1, 16);
        if (lane < 4) {
            spart[d0 * 4 + wm] = s0;
            spart[(d0 + 1) * 4 + wm] = s1;
        }
    }
    __syncthreads();
    if (tid < 64) {
        float s = spart[tid * 4] + spart[tid * 4 + 1] + spart[tid * 4 + 2] + spart[tid * 4 + 3];
        g_part[(b * D + tid) * 128 + mblk] = s;
    }
}

// ---------------------------------------------------------------------------
// K2: rowinv = 1 / sum of 128 per-block partials (deterministic tree)
// ---------------------------------------------------------------------------
__global__ __launch_bounds__(128) void rowinv_kernel()
{
    __shared__ float r[128];
    int row = blockIdx.x, tid = threadIdx.x;
    r[tid] = g_part[row * 128 + tid];
    __syncthreads();
    for (int o = 64; o > 0; o >>= 1) {
        if (tid < o) r[tid] += r[tid + o];
        __syncthreads();
    }
    if (tid == 0) g_rowinv[row] = 1.f / r[0];
}

// ---------------------------------------------------------------------------
// K3: p = e*rowinv; scale = 1/(1e-9+colsum); out = relu(W2@p*scale + bias2 + x)
// Tile 128 pix (M) x 256 c (N in two phases), K=64.  smem ~110KB -> 2 CTAs/SM.
// ---------------------------------------------------------------------------
#define K3_AH 0
#define K3_AL (64 * 272)                 // 17408
#define K3_W  (2 * 64 * 272)             // 34816 ; 2 planes x 256*144
#define K3_RI (K3_W + 73728)             // 108544
#define K3_B2 (K3_RI + 256)
#define K3_CS (K3_B2 + 1024)
#define K3_SC (K3_CS + 2048)
#define K3_SMEM (K3_SC + 512)

__global__ __launch_bounds__(256, 2) void output_kernel(const float* __restrict__ x,
                                                        float* __restrict__ out)
{
    extern __shared__ char sh[];
    uint32_t sb = smem_u32(sh);
    float* ri_s = (float*)(sh + K3_RI);
    float* b2_s = (float*)(sh + K3_B2);
    float* cs   = (float*)(sh + K3_CS);
    float* sc_s = (float*)(sh + K3_SC);
    int tid = threadIdx.x, w = tid >> 5, lane = tid & 31;
    int b = blockIdx.y, pix0 = blockIdx.x * 128;

    if (tid < 64) ri_s[tid] = g_rowinv[b * D + tid];
    b2_s[tid] = g_bias2[tid];
    __syncthreads();

    // stage W2 planes (flat copy)
    {
        const float4* src = (const float4*)g_W2p;
        float4* dst = (float4*)(sh + K3_W);
#pragma unroll
        for (int k = 0; k < 18; k++) {
            int idx = tid + k * 256;
            if (idx < 4608) dst[idx] = src[idx];
        }
    }
    // stage A: p = e * rowinv -> bf16 hi/lo [d][pix]; column partial sums; batched loads
    {
        int p2 = (tid & 63) * 2;
        int dg = tid >> 6;                  // 0..3, 16 d rows each
        const float* ep = g_exp + ((size_t)(b * D + dg * 16)) * NPIX + pix0 + p2;
        char* ahp = sh + K3_AH + (size_t)dg * 16 * 272 + p2 * 2;
        char* alp = sh + K3_AL + (size_t)dg * 16 * 272 + p2 * 2;
        float s0 = 0.f, s1 = 0.f;
#pragma unroll
        for (int jb = 0; jb < 2; jb++) {
            float2 v[8];
#pragma unroll
            for (int u = 0; u < 8; u++)
                v[u] = *(const float2*)(ep + (size_t)(jb * 8 + u) * NPIX);
#pragma unroll
            for (int u = 0; u < 8; u++) {
                int j = jb * 8 + u;
                float ri = ri_s[dg * 16 + j];
                float vx = v[u].x * ri, vy = v[u].y * ri;
                s0 += vx; s1 += vy;
                __nv_bfloat16 h0, l0, h1, l1;
                split_bf16(vx, h0, l0);
                split_bf16(vy, h1, l1);
                __nv_bfloat162 hp; hp.x = h0; hp.y = h1;
                __nv_bfloat162 lp; lp.x = l0; lp.y = l1;
                *(__nv_bfloat162*)(ahp + j * 272) = hp;
                *(__nv_bfloat162*)(alp + j * 272) = lp;
            }
        }
        cs[dg * 128 + p2] = s0;
        cs[dg * 128 + p2 + 1] = s1;
    }
    __syncthreads();
    if (tid < 128)
        sc_s[tid] = 1.f / (1e-9f + cs[tid] + cs[128 + tid] + cs[256 + tid] + cs[384 + tid]);
    __syncthreads();

    int wm = w & 3, wn = w >> 2;
    int m0 = wm * 32;
    uint32_t a_k = (lane & 7) + ((lane >> 4) << 3);
    uint32_t a_mo = ((lane >> 3) & 1) * 8;
    uint32_t b_row = lane & 15;
    uint32_t b_co = (lane >> 4) << 4;

    float scA0 = sc_s[m0 + (lane >> 2)];
    float scB0 = sc_s[m0 + (lane >> 2) + 8];
    float scA1 = sc_s[m0 + 16 + (lane >> 2)];
    float scB1 = sc_s[m0 + 16 + (lane >> 2) + 8];

    for (int ph = 0; ph < 2; ph++) {
        int cb = ph * 128 + wn * 64;
        float acc[2][8][4];
#pragma unroll
        for (int t = 0; t < 2; t++)
#pragma unroll
            for (int q = 0; q < 8; q++)
#pragma unroll
                for (int i = 0; i < 4; i++) acc[t][q][i] = 0.f;

#pragma unroll
        for (int kk = 0; kk < 4; kk++) {
            uint32_t ah[2][4], al[2][4];
#pragma unroll
            for (int t = 0; t < 2; t++) {
                uint32_t off = (kk * 16 + a_k) * 272 + (m0 + t * 16 + a_mo) * 2;
                ldm_x4t(sb + K3_AH + off, ah[t]);
                ldm_x4t(sb + K3_AL + off, al[t]);
            }
#pragma unroll
            for (int q = 0; q < 4; q++) {
                uint32_t off = (cb + q * 16 + b_row) * 144 + kk * 32 + b_co;
                uint32_t bh[4], bl[4];
                ldm_x4(sb + K3_W + off, bh);
                ldm_x4(sb + K3_W + 36864 + off, bl);
#pragma unroll
                for (int t = 0; t < 2; t++) {
                    mma_bf16(acc[t][q * 2], ah[t], bh[0], bh[2]);
                    mma_bf16(acc[t][q * 2], ah[t], bl[0], bl[2]);
                    mma_bf16(acc[t][q * 2], al[t], bh[0], bh[2]);
                    mma_bf16(acc[t][q * 2 + 1], ah[t], bh[1], bh[3]);
                    mma_bf16(acc[t][q * 2 + 1], ah[t], bl[1], bl[3]);
                    mma_bf16(acc[t][q * 2 + 1], al[t], bh[1], bh[3]);
                }
            }
        }

        int prow = pix0 + m0 + (lane >> 2);
#pragma unroll
        for (int t = 0; t < 2; t++) {
            int p0 = prow + t * 16, p1 = p0 + 8;
            float sA = t ? scA1 : scA0;
            float sB = t ? scB1 : scB0;
#pragma unroll
            for (int q = 0; q < 8; q++) {
                int c0 = cb + q * 8 + (lane & 3) * 2;
                float bb0 = b2_s[c0], bb1 = b2_s[c0 + 1];
                const float* x0 = x + ((size_t)(b * C + c0)) * NPIX;
                const float* x1 = x0 + NPIX;
                float* o0 = out + ((size_t)(b * C + c0)) * NPIX;
                float* o1 = o0 + NPIX;
                o0[p0] = fmaxf(fmaf(acc[t][q][0], sA, bb0) + x0[p0], 0.f);
                o1[p0] = fmaxf(fmaf(acc[t][q][1], sA, bb1) + x1[p0], 0.f);
                o0[p1] = fmaxf(fmaf(acc[t][q][2], sB, bb0) + x0[p1], 0.f);
                o1[p1] = fmaxf(fmaf(acc[t][q][3], sB, bb1) + x1[p1], 0.f);
            }
        }
    }
}

// ---------------------------------------------------------------------------
extern "C" void kernel_launch(void* const* d_in, const int* in_sizes, int n_in,
                              void* d_out, int out_size)
{
    const float* x       = (const float*)d_in[0];
    const float* conv1_w = (const float*)d_in[1];
    const float* conv1_b = (const float*)d_in[2];
    const float* mk_w    = (const float*)d_in[3];
    const float* mv_w    = (const float*)d_in[4];
    const float* conv2_w = (const float*)d_in[5];
    const float* gamma   = (const float*)d_in[6];
    const float* beta    = (const float*)d_in[7];
    const float* mean    = (const float*)d_in[8];
    const float* var     = (const float*)d_in[9];
    float* out = (float*)d_out;

    cudaFuncSetAttribute(logits_kernel, cudaFuncAttributeMaxDynamicSharedMemorySize, K1_SMEM);
    cudaFuncSetAttribute(output_kernel, cudaFuncAttributeMaxDynamicSharedMemorySize, K3_SMEM);

    prep_kernel<<<130, 256>>>(conv1_w, conv1_b, mk_w, mv_w, conv2_w,
                              gamma, beta, mean, var);

    dim3 g1(NPIX / 128, BATCH);
    logits_kernel<<<g1, 256, K1_SMEM>>>(x);

    rowinv_kernel<<<BATCH * D, 128>>>();

    dim3 g3(NPIX / 128, BATCH);
    output_kernel<<<g3, 256, K3_SMEM>>>(x, out);
}